// round 2
// baseline (speedup 1.0000x reference)
#include <cuda_runtime.h>
#include <cuda_bf16.h>
#include <cstdint>

// Problem constants
#define PN 2
#define PT 16
#define PS 256
#define PD 1024
#define PM (PN * PT * PS)     // 8192 rows
#define C3D (3 * PD)          // 3072
#define HEADS 8
#define DH 64
#define SCALE 0.125f

// Scratch (device globals; no cudaMalloc allowed)
__device__ float g_qkv[(size_t)PM * C3D];   // [8192, 3072]
__device__ float g_att[(size_t)PM * PD];    // [8192, 1024] concat(x_s, x_t)

// ---------------------------------------------------------------------------
// SGEMM: C[M,N] = A[M,K] @ B[K,N] (+ bias). BM=BN=128, BK=8, 256 thr, 8x8/thr
// ---------------------------------------------------------------------------
template <bool BIAS>
__global__ __launch_bounds__(256)
void sgemm128(const float* __restrict__ A, const float* __restrict__ B,
              const float* __restrict__ bias, float* __restrict__ C,
              int M, int Nn, int K) {
    __shared__ float As[8][128];
    __shared__ float Bs[8][128];

    const int tid = threadIdx.x;
    const int bm = blockIdx.y, bn = blockIdx.x;

    const int a_row  = tid >> 1;          // 0..127
    const int a_col4 = (tid & 1) * 4;     // 0 or 4
    const int b_row  = tid >> 5;          // 0..7
    const int b_col4 = (tid & 31) * 4;    // 0..124

    const int tx = tid & 15;              // col group
    const int ty = tid >> 4;              // row group

    const float* Ab = A + (size_t)(bm * 128) * K;
    const float* Bb = B + bn * 128;

    float acc[8][8];
#pragma unroll
    for (int i = 0; i < 8; i++)
#pragma unroll
        for (int j = 0; j < 8; j++) acc[i][j] = 0.f;

    for (int k0 = 0; k0 < K; k0 += 8) {
        float4 av = *(const float4*)(Ab + (size_t)a_row * K + k0 + a_col4);
        As[a_col4 + 0][a_row] = av.x;
        As[a_col4 + 1][a_row] = av.y;
        As[a_col4 + 2][a_row] = av.z;
        As[a_col4 + 3][a_row] = av.w;
        float4 bv = *(const float4*)(Bb + (size_t)(k0 + b_row) * Nn + b_col4);
        *(float4*)&Bs[b_row][b_col4] = bv;
        __syncthreads();

#pragma unroll
        for (int k = 0; k < 8; k++) {
            float4 a0 = *(const float4*)&As[k][ty * 8];
            float4 a1 = *(const float4*)&As[k][ty * 8 + 4];
            float4 b0 = *(const float4*)&Bs[k][tx * 8];
            float4 b1 = *(const float4*)&Bs[k][tx * 8 + 4];
            float ar[8] = {a0.x, a0.y, a0.z, a0.w, a1.x, a1.y, a1.z, a1.w};
            float br[8] = {b0.x, b0.y, b0.z, b0.w, b1.x, b1.y, b1.z, b1.w};
#pragma unroll
            for (int i = 0; i < 8; i++)
#pragma unroll
                for (int j = 0; j < 8; j++)
                    acc[i][j] = fmaf(ar[i], br[j], acc[i][j]);
        }
        __syncthreads();
    }

    float bb[8];
    if (BIAS) {
#pragma unroll
        for (int j = 0; j < 8; j++) bb[j] = bias[bn * 128 + tx * 8 + j];
    }
#pragma unroll
    for (int i = 0; i < 8; i++) {
        float* Crow = C + (size_t)(bm * 128 + ty * 8 + i) * Nn + bn * 128 + tx * 8;
        float4 v0, v1;
        v0.x = acc[i][0]; v0.y = acc[i][1]; v0.z = acc[i][2]; v0.w = acc[i][3];
        v1.x = acc[i][4]; v1.y = acc[i][5]; v1.z = acc[i][6]; v1.w = acc[i][7];
        if (BIAS) {
            v0.x += bb[0]; v0.y += bb[1]; v0.z += bb[2]; v0.w += bb[3];
            v1.x += bb[4]; v1.y += bb[5]; v1.z += bb[6]; v1.w += bb[7];
        }
        *(float4*)(Crow)     = v0;
        *(float4*)(Crow + 4) = v1;
    }
}

// ---------------------------------------------------------------------------
// Spatial attention: block = (head h, frame nt). Q rows: one per thread (256).
// K,V [256,64] staged in dynamic smem (128 KB). Two-pass softmax (recompute).
// qkv layout per row: [q_s(512) | q_t(512) | k_s | k_t | v_s | v_t]
// ---------------------------------------------------------------------------
__global__ __launch_bounds__(256)
void spatial_attn_kernel() {
    extern __shared__ float sm[];
    float* Ks = sm;                 // [256][64]
    float* Vs = sm + PS * DH;       // [256][64]

    const int h  = blockIdx.x;      // 0..7
    const int nt = blockIdx.y;      // 0..31
    const int tid = threadIdx.x;    // 0..255 = query index

    const float* base = g_qkv + (size_t)nt * PS * C3D;

    // cooperative K/V load (float4)
    for (int i = tid; i < PS * DH / 4; i += 256) {
        int s  = i >> 4;            // 16 float4 per row
        int d4 = (i & 15) * 4;
        *(float4*)&Ks[s * DH + d4] =
            *(const float4*)(base + (size_t)s * C3D + 1024 + h * DH + d4);
        *(float4*)&Vs[s * DH + d4] =
            *(const float4*)(base + (size_t)s * C3D + 2048 + h * DH + d4);
    }
    __syncthreads();

    float q[DH];
    const float* qp = base + (size_t)tid * C3D + h * DH;   // q_s
#pragma unroll
    for (int d = 0; d < DH; d++) q[d] = qp[d] * SCALE;

    // pass 1: running max + sum of exp
    float mmax = -1e30f, lsum = 0.f;
    for (int j = 0; j < PS; j++) {
        float dot = 0.f;
        const float* kr = &Ks[j * DH];
#pragma unroll
        for (int d = 0; d < DH; d++) dot = fmaf(q[d], kr[d], dot);
        float nm = fmaxf(mmax, dot);
        lsum = lsum * __expf(mmax - nm) + __expf(dot - nm);
        mmax = nm;
    }
    const float inv = 1.f / lsum;

    // pass 2: weighted sum of V (recompute logits)
    float accv[DH];
#pragma unroll
    for (int d = 0; d < DH; d++) accv[d] = 0.f;
    for (int j = 0; j < PS; j++) {
        float dot = 0.f;
        const float* kr = &Ks[j * DH];
#pragma unroll
        for (int d = 0; d < DH; d++) dot = fmaf(q[d], kr[d], dot);
        float w = __expf(dot - mmax) * inv;
        const float* vr = &Vs[j * DH];
#pragma unroll
        for (int d = 0; d < DH; d++) accv[d] = fmaf(w, vr[d], accv[d]);
    }

    float* op = g_att + ((size_t)nt * PS + tid) * PD + h * DH;  // cols [0,512)
#pragma unroll
    for (int d4 = 0; d4 < DH; d4 += 4) {
        float4 v; v.x = accv[d4]; v.y = accv[d4+1]; v.z = accv[d4+2]; v.w = accv[d4+3];
        *(float4*)(op + d4) = v;
    }
}

// ---------------------------------------------------------------------------
// Temporal attention: block = (n, s). 128 threads = 16 t-queries x 8 heads.
// T=16 logits fit in registers; K/V rows read directly (L1-cached).
// ---------------------------------------------------------------------------
__global__ __launch_bounds__(128)
void temporal_attn_kernel() {
    const int ns = blockIdx.x;          // 0..511
    const int n  = ns >> 8;
    const int s  = ns & 255;
    const int tid = threadIdx.x;
    const int tq = tid & 15;            // query t
    const int h  = tid >> 4;            // head

    auto row = [&](int t) -> size_t {
        return ((size_t)(n * PT + t) * PS + s) * C3D;
    };

    float q[DH];
    const float* qp = g_qkv + row(tq) + 512 + h * DH;     // q_t
#pragma unroll
    for (int d = 0; d < DH; d++) q[d] = qp[d] * SCALE;

    float lg[PT];
    float mmax = -1e30f;
#pragma unroll
    for (int tk = 0; tk < PT; tk++) {
        const float* kp = g_qkv + row(tk) + 1536 + h * DH;  // k_t
        float dot = 0.f;
#pragma unroll
        for (int d4 = 0; d4 < DH; d4 += 4) {
            float4 kv = *(const float4*)(kp + d4);
            dot = fmaf(q[d4+0], kv.x, dot);
            dot = fmaf(q[d4+1], kv.y, dot);
            dot = fmaf(q[d4+2], kv.z, dot);
            dot = fmaf(q[d4+3], kv.w, dot);
        }
        lg[tk] = dot;
        mmax = fmaxf(mmax, dot);
    }
    float lsum = 0.f;
#pragma unroll
    for (int tk = 0; tk < PT; tk++) { lg[tk] = __expf(lg[tk] - mmax); lsum += lg[tk]; }
    const float inv = 1.f / lsum;

    float accv[DH];
#pragma unroll
    for (int d = 0; d < DH; d++) accv[d] = 0.f;
#pragma unroll
    for (int tk = 0; tk < PT; tk++) {
        const float w = lg[tk] * inv;
        const float* vp = g_qkv + row(tk) + 2560 + h * DH;  // v_t
#pragma unroll
        for (int d4 = 0; d4 < DH; d4 += 4) {
            float4 vv = *(const float4*)(vp + d4);
            accv[d4+0] = fmaf(w, vv.x, accv[d4+0]);
            accv[d4+1] = fmaf(w, vv.y, accv[d4+1]);
            accv[d4+2] = fmaf(w, vv.z, accv[d4+2]);
            accv[d4+3] = fmaf(w, vv.w, accv[d4+3]);
        }
    }

    float* op = g_att + ((size_t)(n * PT + tq) * PS + s) * PD + 512 + h * DH; // cols [512,1024)
#pragma unroll
    for (int d4 = 0; d4 < DH; d4 += 4) {
        float4 v; v.x = accv[d4]; v.y = accv[d4+1]; v.z = accv[d4+2]; v.w = accv[d4+3];
        *(float4*)(op + d4) = v;
    }
}

// ---------------------------------------------------------------------------
// Host launcher
// ---------------------------------------------------------------------------
extern "C" void kernel_launch(void* const* d_in, const int* in_sizes, int n_in,
                              void* d_out, int out_size) {
    (void)in_sizes; (void)n_in; (void)out_size;
    const float* x     = (const float*)d_in[0];
    const float* Wqkv  = (const float*)d_in[1];
    const float* Wproj = (const float*)d_in[2];
    const float* bproj = (const float*)d_in[3];
    float* out = (float*)d_out;

    void* qkv_p = nullptr; void* att_p = nullptr;
    cudaGetSymbolAddress(&qkv_p, g_qkv);
    cudaGetSymbolAddress(&att_p, g_att);
    float* qkv = (float*)qkv_p;
    float* att = (float*)att_p;

    // GEMM1: qkv = x @ Wqkv   [8192,1024] x [1024,3072]
    sgemm128<false><<<dim3(C3D / 128, PM / 128), 256>>>(x, Wqkv, nullptr, qkv,
                                                        PM, C3D, PD);

    // Spatial attention (128 KB dynamic smem)
    cudaFuncSetAttribute(spatial_attn_kernel,
                         cudaFuncAttributeMaxDynamicSharedMemorySize,
                         2 * PS * DH * (int)sizeof(float));
    spatial_attn_kernel<<<dim3(HEADS, PN * PT), 256,
                          2 * PS * DH * sizeof(float)>>>();

    // Temporal attention
    temporal_attn_kernel<<<PN * PS, 128>>>();

    // GEMM2: out = att @ Wproj + bproj   [8192,1024] x [1024,1024]
    sgemm128<true><<<dim3(PD / 128, PM / 128), 256>>>(att, Wproj, bproj, out,
                                                      PM, PD, PD);
}

// round 5
// speedup vs baseline: 2.1216x; 2.1216x over previous
#include <cuda_runtime.h>
#include <cuda_fp16.h>
#include <cstdint>

// ---------------------------------------------------------------------------
// Problem constants
// ---------------------------------------------------------------------------
#define PN 2
#define PT 16
#define PS 256
#define PD 1024
#define PM (PN * PT * PS)     // 8192
#define C3D (3 * PD)          // 3072
#define HEADS 8
#define DH 64
#define SCALE 0.125f

// GEMM tiling
#define BM 128
#define BN 128
#define BK 32
#define SSTR 40               // smem row stride in halfs (80B, conflict-free ldmatrix)

// ---------------------------------------------------------------------------
// Scratch (device globals; no cudaMalloc allowed)
// ---------------------------------------------------------------------------
__device__ float g_qkv[(size_t)PM * C3D];        // [8192,3072] fp32
__device__ float g_att[(size_t)PM * PD];         // [8192,1024] fp32
__device__ __half g_x16[(size_t)PM * PD];        // x fp16
__device__ __half g_a16[(size_t)PM * PD];        // att fp16
__device__ __half g_wq16[(size_t)C3D * PD];      // Wqkv^T [3072,1024] fp16
__device__ __half g_wp16[(size_t)PD * PD];       // Wproj^T [1024,1024] fp16

// ---------------------------------------------------------------------------
// HMMA GEMM: C[M,Nn] = A[M,K](fp16) @ Bt[Nn,K](fp16)^T (+bias), fp32 accum.
// 256 threads, 8 warps (2x4), warp tile 64x32, m16n8k16 mma + ldmatrix.
// ---------------------------------------------------------------------------
__device__ __forceinline__ void ldmx4(uint32_t* r, uint32_t addr) {
    asm volatile(
        "ldmatrix.sync.aligned.m8n8.x4.shared.b16 {%0,%1,%2,%3}, [%4];"
        : "=r"(r[0]), "=r"(r[1]), "=r"(r[2]), "=r"(r[3]) : "r"(addr));
}
__device__ __forceinline__ void mma16816(float* c, const uint32_t* a,
                                         const uint32_t* b) {
    asm volatile(
        "mma.sync.aligned.m16n8k16.row.col.f32.f16.f16.f32 "
        "{%0,%1,%2,%3}, {%4,%5,%6,%7}, {%8,%9}, {%0,%1,%2,%3};"
        : "+f"(c[0]), "+f"(c[1]), "+f"(c[2]), "+f"(c[3])
        : "r"(a[0]), "r"(a[1]), "r"(a[2]), "r"(a[3]), "r"(b[0]), "r"(b[1]));
}

template <bool BIAS>
__global__ __launch_bounds__(256, 2)
void gemm_mma(const __half* __restrict__ A, const __half* __restrict__ Bt,
              const float* __restrict__ bias, float* __restrict__ C,
              int Nn, int K) {
    __shared__ __half sA[BM * SSTR];
    __shared__ __half sB[BN * SSTR];

    const int tid = threadIdx.x;
    const int wid = tid >> 5, lane = tid & 31;
    const int wm = wid & 1;               // 0..1 -> 64 rows each
    const int wn = wid >> 1;              // 0..3 -> 32 cols each
    const int bm = blockIdx.y, bn = blockIdx.x;

    const __half* gA = A + (size_t)(bm * BM) * K;
    const __half* gB = Bt + (size_t)(bn * BN) * K;

    // global load mapping: 2 x uint4 (8 halfs) per thread per tile
    const int r0 = tid >> 2, s0 = (tid & 3) * 8;              // item 0
    const int r1 = (tid + 256) >> 2, s1 = s0;                 // item 1 (same seg)

    // ldmatrix per-lane addresses (byte offsets into sA/sB)
    const uint32_t aBase = (uint32_t)__cvta_generic_to_shared(sA);
    const uint32_t bBase = (uint32_t)__cvta_generic_to_shared(sB);
    const int aRow = (lane & 15);
    const int aK   = (lane >> 4) * 8;
    const int bRow = ((lane >> 4) * 8) + (lane & 7);
    const int bK   = ((lane >> 3) & 1) * 8;

    float acc[4][4][4];
#pragma unroll
    for (int i = 0; i < 4; i++)
#pragma unroll
        for (int j = 0; j < 4; j++)
#pragma unroll
            for (int k = 0; k < 4; k++) acc[i][j][k] = 0.f;

    const int nch = K / BK;

    // preload chunk 0
    {
        uint4 va0 = *(const uint4*)(gA + (size_t)r0 * K + s0);
        uint4 va1 = *(const uint4*)(gA + (size_t)r1 * K + s1);
        uint4 vb0 = *(const uint4*)(gB + (size_t)r0 * K + s0);
        uint4 vb1 = *(const uint4*)(gB + (size_t)r1 * K + s1);
        *(uint4*)(sA + r0 * SSTR + s0) = va0;
        *(uint4*)(sA + r1 * SSTR + s1) = va1;
        *(uint4*)(sB + r0 * SSTR + s0) = vb0;
        *(uint4*)(sB + r1 * SSTR + s1) = vb1;
    }
    __syncthreads();

    for (int c = 0; c < nch; c++) {
        // prefetch next chunk into registers (overlaps with MMA below)
        uint4 na0, na1, nb0, nb1;
        if (c + 1 < nch) {
            const int ko = (c + 1) * BK;
            na0 = *(const uint4*)(gA + (size_t)r0 * K + ko + s0);
            na1 = *(const uint4*)(gA + (size_t)r1 * K + ko + s1);
            nb0 = *(const uint4*)(gB + (size_t)r0 * K + ko + s0);
            nb1 = *(const uint4*)(gB + (size_t)r1 * K + ko + s1);
        }

        // compute chunk c: 2 k16 steps
#pragma unroll
        for (int ks = 0; ks < 2; ks++) {
            uint32_t af[4][4], bf[4][2];
#pragma unroll
            for (int mt = 0; mt < 4; mt++) {
                const uint32_t ad = aBase +
                    ((wm * 64 + mt * 16 + aRow) * SSTR + ks * 16 + aK) * 2;
                ldmx4(af[mt], ad);
            }
#pragma unroll
            for (int tp = 0; tp < 2; tp++) {
                const uint32_t bd = bBase +
                    ((wn * 32 + tp * 16 + bRow) * SSTR + ks * 16 + bK) * 2;
                uint32_t t[4];
                ldmx4(t, bd);
                bf[tp * 2][0] = t[0]; bf[tp * 2][1] = t[1];
                bf[tp * 2 + 1][0] = t[2]; bf[tp * 2 + 1][1] = t[3];
            }
#pragma unroll
            for (int mt = 0; mt < 4; mt++)
#pragma unroll
                for (int nt = 0; nt < 4; nt++)
                    mma16816(acc[mt][nt], af[mt], bf[nt]);
        }
        __syncthreads();
        if (c + 1 < nch) {
            *(uint4*)(sA + r0 * SSTR + s0) = na0;
            *(uint4*)(sA + r1 * SSTR + s1) = na1;
            *(uint4*)(sB + r0 * SSTR + s0) = nb0;
            *(uint4*)(sB + r1 * SSTR + s1) = nb1;
        }
        __syncthreads();
    }

    // epilogue
    const int gr = lane >> 2, gc2 = (lane & 3) * 2;
#pragma unroll
    for (int mt = 0; mt < 4; mt++) {
        const int row = bm * BM + wm * 64 + mt * 16 + gr;
#pragma unroll
        for (int nt = 0; nt < 4; nt++) {
            const int col = bn * BN + wn * 32 + nt * 8 + gc2;
            float b0 = 0.f, b1 = 0.f;
            if (BIAS) { b0 = bias[col]; b1 = bias[col + 1]; }
            float2 v0, v1;
            v0.x = acc[mt][nt][0] + b0; v0.y = acc[mt][nt][1] + b1;
            v1.x = acc[mt][nt][2] + b0; v1.y = acc[mt][nt][3] + b1;
            *(float2*)(C + (size_t)row * Nn + col)       = v0;
            *(float2*)(C + (size_t)(row + 8) * Nn + col) = v1;
        }
    }
}

// ---------------------------------------------------------------------------
// fp32 -> fp16 convert (vectorized)
// ---------------------------------------------------------------------------
__global__ __launch_bounds__(256)
void conv16_kernel(const float* __restrict__ in, __half* __restrict__ out,
                   size_t n4) {
    size_t i = (size_t)blockIdx.x * blockDim.x + threadIdx.x;
    if (i >= n4) return;
    i *= 4;
    float4 v = *(const float4*)(in + i);
    __half2 h0 = __floats2half2_rn(v.x, v.y);
    __half2 h1 = __floats2half2_rn(v.z, v.w);
    *(__half2*)(out + i)     = h0;
    *(__half2*)(out + i + 2) = h1;
}

// ---------------------------------------------------------------------------
// Transpose + convert: W[K,N] fp32 -> T[N,K] fp16
// ---------------------------------------------------------------------------
__global__ __launch_bounds__(256)
void tconv_kernel(const float* __restrict__ W, __half* __restrict__ T,
                  int K, int N) {
    __shared__ float tile[32][33];
    const int tx = threadIdx.x, ty = threadIdx.y;   // 32 x 8
    const int bx = blockIdx.x, by = blockIdx.y;     // N/32, K/32
#pragma unroll
    for (int r = 0; r < 32; r += 8)
        tile[ty + r][tx] = W[(size_t)(by * 32 + ty + r) * N + bx * 32 + tx];
    __syncthreads();
#pragma unroll
    for (int r = 0; r < 32; r += 8) {
        const size_t o = (size_t)(bx * 32 + ty + r) * K + by * 32 + tx;
        T[o] = __float2half_rn(tile[tx][ty + r]);
    }
}

// ---------------------------------------------------------------------------
// Spatial attention (unchanged from R2 baseline)
// ---------------------------------------------------------------------------
__global__ __launch_bounds__(256)
void spatial_attn_kernel() {
    extern __shared__ float sm[];
    float* Ks = sm;
    float* Vs = sm + PS * DH;

    const int h  = blockIdx.x;
    const int nt = blockIdx.y;
    const int tid = threadIdx.x;

    const float* base = g_qkv + (size_t)nt * PS * C3D;

    for (int i = tid; i < PS * DH / 4; i += 256) {
        int s  = i >> 4;
        int d4 = (i & 15) * 4;
        *(float4*)&Ks[s * DH + d4] =
            *(const float4*)(base + (size_t)s * C3D + 1024 + h * DH + d4);
        *(float4*)&Vs[s * DH + d4] =
            *(const float4*)(base + (size_t)s * C3D + 2048 + h * DH + d4);
    }
    __syncthreads();

    float q[DH];
    const float* qp = base + (size_t)tid * C3D + h * DH;
#pragma unroll
    for (int d = 0; d < DH; d++) q[d] = qp[d] * SCALE;

    float mmax = -1e30f, lsum = 0.f;
    for (int j = 0; j < PS; j++) {
        float dot = 0.f;
        const float* kr = &Ks[j * DH];
#pragma unroll
        for (int d = 0; d < DH; d++) dot = fmaf(q[d], kr[d], dot);
        float nm = fmaxf(mmax, dot);
        lsum = lsum * __expf(mmax - nm) + __expf(dot - nm);
        mmax = nm;
    }
    const float inv = 1.f / lsum;

    float accv[DH];
#pragma unroll
    for (int d = 0; d < DH; d++) accv[d] = 0.f;
    for (int j = 0; j < PS; j++) {
        float dot = 0.f;
        const float* kr = &Ks[j * DH];
#pragma unroll
        for (int d = 0; d < DH; d++) dot = fmaf(q[d], kr[d], dot);
        float w = __expf(dot - mmax) * inv;
        const float* vr = &Vs[j * DH];
#pragma unroll
        for (int d = 0; d < DH; d++) accv[d] = fmaf(w, vr[d], accv[d]);
    }

    float* op = g_att + ((size_t)nt * PS + tid) * PD + h * DH;
#pragma unroll
    for (int d4 = 0; d4 < DH; d4 += 4) {
        float4 v; v.x = accv[d4]; v.y = accv[d4+1]; v.z = accv[d4+2]; v.w = accv[d4+3];
        *(float4*)(op + d4) = v;
    }
}

// ---------------------------------------------------------------------------
// Temporal attention (unchanged from R2 baseline)
// ---------------------------------------------------------------------------
__global__ __launch_bounds__(128)
void temporal_attn_kernel() {
    const int ns = blockIdx.x;
    const int n  = ns >> 8;
    const int s  = ns & 255;
    const int tid = threadIdx.x;
    const int tq = tid & 15;
    const int h  = tid >> 4;

    auto row = [&](int t) -> size_t {
        return ((size_t)(n * PT + t) * PS + s) * C3D;
    };

    float q[DH];
    const float* qp = g_qkv + row(tq) + 512 + h * DH;
#pragma unroll
    for (int d = 0; d < DH; d++) q[d] = qp[d] * SCALE;

    float lg[PT];
    float mmax = -1e30f;
#pragma unroll
    for (int tk = 0; tk < PT; tk++) {
        const float* kp = g_qkv + row(tk) + 1536 + h * DH;
        float dot = 0.f;
#pragma unroll
        for (int d4 = 0; d4 < DH; d4 += 4) {
            float4 kv = *(const float4*)(kp + d4);
            dot = fmaf(q[d4+0], kv.x, dot);
            dot = fmaf(q[d4+1], kv.y, dot);
            dot = fmaf(q[d4+2], kv.z, dot);
            dot = fmaf(q[d4+3], kv.w, dot);
        }
        lg[tk] = dot;
        mmax = fmaxf(mmax, dot);
    }
    float lsum = 0.f;
#pragma unroll
    for (int tk = 0; tk < PT; tk++) { lg[tk] = __expf(lg[tk] - mmax); lsum += lg[tk]; }
    const float inv = 1.f / lsum;

    float accv[DH];
#pragma unroll
    for (int d = 0; d < DH; d++) accv[d] = 0.f;
#pragma unroll
    for (int tk = 0; tk < PT; tk++) {
        const float w = lg[tk] * inv;
        const float* vp = g_qkv + row(tk) + 2560 + h * DH;
#pragma unroll
        for (int d4 = 0; d4 < DH; d4 += 4) {
            float4 vv = *(const float4*)(vp + d4);
            accv[d4+0] = fmaf(w, vv.x, accv[d4+0]);
            accv[d4+1] = fmaf(w, vv.y, accv[d4+1]);
            accv[d4+2] = fmaf(w, vv.z, accv[d4+2]);
            accv[d4+3] = fmaf(w, vv.w, accv[d4+3]);
        }
    }

    float* op = g_att + ((size_t)(n * PT + tq) * PS + s) * PD + 512 + h * DH;
#pragma unroll
    for (int d4 = 0; d4 < DH; d4 += 4) {
        float4 v; v.x = accv[d4]; v.y = accv[d4+1]; v.z = accv[d4+2]; v.w = accv[d4+3];
        *(float4*)(op + d4) = v;
    }
}

// ---------------------------------------------------------------------------
// Host launcher
// ---------------------------------------------------------------------------
extern "C" void kernel_launch(void* const* d_in, const int* in_sizes, int n_in,
                              void* d_out, int out_size) {
    (void)in_sizes; (void)n_in; (void)out_size;
    const float* x     = (const float*)d_in[0];
    const float* Wqkv  = (const float*)d_in[1];
    const float* Wproj = (const float*)d_in[2];
    const float* bproj = (const float*)d_in[3];
    float* out = (float*)d_out;

    void *p_qkv, *p_att, *p_x16, *p_a16, *p_wq16, *p_wp16;
    cudaGetSymbolAddress(&p_qkv,  g_qkv);
    cudaGetSymbolAddress(&p_att,  g_att);
    cudaGetSymbolAddress(&p_x16,  g_x16);
    cudaGetSymbolAddress(&p_a16,  g_a16);
    cudaGetSymbolAddress(&p_wq16, g_wq16);
    cudaGetSymbolAddress(&p_wp16, g_wp16);

    cudaFuncSetAttribute(spatial_attn_kernel,
                         cudaFuncAttributeMaxDynamicSharedMemorySize,
                         2 * PS * DH * (int)sizeof(float));

    const size_t n4 = (size_t)PM * PD / 4;
    const int sgrid = (int)((n4 + 255) / 256);

    // 1) convert inputs to fp16 (weights transposed to [N,K])
    conv16_kernel<<<sgrid, 256>>>(x, (__half*)p_x16, n4);
    tconv_kernel<<<dim3(C3D / 32, PD / 32), dim3(32, 8)>>>(Wqkv, (__half*)p_wq16,
                                                           PD, C3D);
    tconv_kernel<<<dim3(PD / 32, PD / 32), dim3(32, 8)>>>(Wproj, (__half*)p_wp16,
                                                          PD, PD);

    // 2) GEMM1: qkv = x @ Wqkv (HMMA fp16, fp32 accum)
    gemm_mma<false><<<dim3(C3D / BN, PM / BM), 256>>>(
        (const __half*)p_x16, (const __half*)p_wq16, nullptr, (float*)p_qkv,
        C3D, PD);

    // 3) attention
    spatial_attn_kernel<<<dim3(HEADS, PN * PT), 256, 2 * PS * DH * sizeof(float)>>>();
    temporal_attn_kernel<<<PN * PS, 128>>>();

    // 4) convert att, GEMM2: out = att @ Wproj + b
    conv16_kernel<<<sgrid, 256>>>((const float*)p_att, (__half*)p_a16, n4);
    gemm_mma<true><<<dim3(PD / BN, PM / BM), 256>>>(
        (const __half*)p_a16, (const __half*)p_wp16, bproj, out, PD, PD);
}